// round 1
// baseline (speedup 1.0000x reference)
#include <cuda_runtime.h>
#include <cuda_bf16.h>
#include <math.h>

// ============================================================================
// quantizer: out = center[argmin_m |x - center[m]|]   (W_hard; the reference's
// (W_hard - W_soft) + W_soft equals W_hard up to 1 ulp).
//
// Strategy: nearest-center of 16 sorted centers is a monotone step function of
// x with 15 breakpoints. Prep kernel computes the EXACT fp32 crossover of each
// breakpoint (replicating the reference's fp32 |x-c| compares + argmin
// first-index tie rule), then builds a 4096-entry uniform LUT of
// (thr, c_left, c_right, pad). Main kernel: one FFMA + clamp-convert + one
// LDS.128 + one predicated select per element.
// ============================================================================

#define LUT_SIZE 4096
#define LUT_BYTES (LUT_SIZE * 16)

__device__ float4 g_lut[LUT_SIZE];
__device__ float  g_scale;   // t = x * g_scale + g_bias ; cell = (rn(t) & ~15)/16
__device__ float  g_bias;

// ---------------------------------------------------------------------------
// Prep kernel: one block. Thread 0 sorts centers + finds exact crossovers;
// all threads fill the global LUT.
// ---------------------------------------------------------------------------
__global__ void quant_prep_kernel(const float* __restrict__ center)
{
    __shared__ float  s_cs[16];     // sorted centers
    __shared__ float  s_mid[15];    // midpoints (approx breakpoints)
    __shared__ float  s_cross[15];  // exact fp32 crossover: x < cross -> left
    __shared__ float  s_scale, s_bias;

    if (threadIdx.x == 0) {
        float c[16];
        int   oi[16];
        for (int i = 0; i < 16; i++) { c[i] = center[i]; oi[i] = i; }
        // insertion sort (stable), keep original indices for the tie rule
        for (int i = 1; i < 16; i++) {
            float v = c[i]; int ix = oi[i]; int j = i - 1;
            while (j >= 0 && c[j] > v) { c[j+1] = c[j]; oi[j+1] = oi[j]; j--; }
            c[j+1] = v; oi[j+1] = ix;
        }
        for (int i = 0; i < 16; i++) s_cs[i] = c[i];
        for (int k = 0; k < 15; k++) s_mid[k] = 0.5f * (c[k] + c[k+1]);

        float span = s_mid[14] - s_mid[0];
        if (!(span > 0.0f)) span = 1e-6f;
        float step  = span / (float)(LUT_SIZE - 80);   // leave 40-cell margins
        float lo    = s_mid[0] - 40.0f * step;
        float scale = 16.0f / step;                    // 16 code units per cell
        float bias  = -lo * scale;
        s_scale = scale;  s_bias = bias;
        g_scale = scale;  g_bias = bias;

        // Exact crossover per breakpoint: smallest fp32 x for which the
        // reference picks the RIGHT center. pick_left(x) is monotone
        // (true then false), so bisect to adjacent floats.
        for (int k = 0; k < 15; k++) {
            float cl = c[k], cr = c[k+1];
            int   ol = oi[k], orr = oi[k+1];
            float a = s_mid[k] - 2.0f * step;
            float b = s_mid[k] + 2.0f * step;
            // replicate: dl = |x-cl|, dr = |x-cr|; left wins if dl<dr, or
            // dl==dr and ol<orr (argmin returns first original index).
            for (int it = 0; it < 80; it++) {
                float m = 0.5f * (a + b);
                if (m <= a || m >= b) break;
                float dl = fabsf(m - cl), dr = fabsf(m - cr);
                bool pick_left = (dl < dr) || (dl == dr && ol < orr);
                if (pick_left) a = m; else b = m;
            }
            s_cross[k] = b;
        }
    }
    __syncthreads();

    const float scale = s_scale, bias = s_bias;
    const float inv   = 1.0f / scale;
    const float PINF  = __int_as_float(0x7f800000);

    for (int i = threadIdx.x; i < LUT_SIZE; i += blockDim.x) {
        // t-window of cell i (rn rounding window [16i-0.5, 16i+15.5] + margin)
        float tlo = 16.0f * (float)i - 1.5f;
        float thi = 16.0f * (float)i + 17.0f;
        float xlo = (tlo - bias) * inv;
        float xhi = (thi - bias) * inv;

        int kfound = -1, cnt = 0;
        for (int k = 0; k < 15; k++)
            if (s_mid[k] >= xlo && s_mid[k] <= xhi) { if (kfound < 0) kfound = k; cnt++; }

        float4 e;
        if (cnt == 0) {
            // whole cell inside one region: count crossovers below cell center
            float xc = 0.5f * (xlo + xhi);
            int r = 0;
            for (int k = 0; k < 15; k++) if (s_cross[k] <= xc) r++;
            e = make_float4(PINF, s_cs[r], s_cs[r], 0.0f);
        } else {
            int k = kfound;
            if (cnt > 1) {  // pick breakpoint nearest cell center (rare; exactness
                            // assumes <=1 per cell — revisit if rel_err fails)
                float xc = 0.5f * (xlo + xhi);
                float best = fabsf(s_mid[k] - xc);
                for (int k2 = kfound + 1; k2 < 15; k2++)
                    if (s_mid[k2] >= xlo && s_mid[k2] <= xhi) {
                        float d = fabsf(s_mid[k2] - xc);
                        if (d < best) { best = d; k = k2; }
                    }
            }
            e = make_float4(s_cross[k], s_cs[k], s_cs[k+1], 0.0f);
        }
        g_lut[i] = e;
    }
}

// ---------------------------------------------------------------------------
// Main kernel: LUT in shared memory, float4 grid-stride with 4-deep MLP.
// ---------------------------------------------------------------------------
__device__ __forceinline__ float quant_one(float x, float scale, float bias,
                                           const char* slut)
{
    float t = fmaf(x, scale, bias);
    unsigned code = __float2uint_rn(t);        // negatives -> 0 (saturating)
    code = umin(code, 65535u);
    unsigned off = code & 0xFFF0u;             // byte offset of 16B entry
    float4 e = *reinterpret_cast<const float4*>(slut + off);
    return (x < e.x) ? e.y : e.z;
}

extern "C" __global__ void __launch_bounds__(1024, 2)
quant_main_kernel(const float4* __restrict__ x, float4* __restrict__ out, int n4)
{
    extern __shared__ float4 slut[];
    // load LUT (64 KB) into shared
    #pragma unroll
    for (int i = threadIdx.x; i < LUT_SIZE; i += 1024)
        slut[i] = g_lut[i];
    const float scale = g_scale;
    const float bias  = g_bias;
    __syncthreads();

    const char* lutb = reinterpret_cast<const char*>(slut);
    const int stride = gridDim.x * blockDim.x;
    int i = blockIdx.x * blockDim.x + threadIdx.x;

    // 4-deep unrolled grid-stride: front-batched LDG.128 for MLP
    for (; i + 3 * stride < n4; i += 4 * stride) {
        float4 a = x[i];
        float4 b = x[i + stride];
        float4 c = x[i + 2 * stride];
        float4 d = x[i + 3 * stride];

        float4 ra, rb, rc, rd;
        ra.x = quant_one(a.x, scale, bias, lutb);
        ra.y = quant_one(a.y, scale, bias, lutb);
        ra.z = quant_one(a.z, scale, bias, lutb);
        ra.w = quant_one(a.w, scale, bias, lutb);
        rb.x = quant_one(b.x, scale, bias, lutb);
        rb.y = quant_one(b.y, scale, bias, lutb);
        rb.z = quant_one(b.z, scale, bias, lutb);
        rb.w = quant_one(b.w, scale, bias, lutb);
        rc.x = quant_one(c.x, scale, bias, lutb);
        rc.y = quant_one(c.y, scale, bias, lutb);
        rc.z = quant_one(c.z, scale, bias, lutb);
        rc.w = quant_one(c.w, scale, bias, lutb);
        rd.x = quant_one(d.x, scale, bias, lutb);
        rd.y = quant_one(d.y, scale, bias, lutb);
        rd.z = quant_one(d.z, scale, bias, lutb);
        rd.w = quant_one(d.w, scale, bias, lutb);

        out[i]              = ra;
        out[i + stride]     = rb;
        out[i + 2 * stride] = rc;
        out[i + 3 * stride] = rd;
    }
    for (; i < n4; i += stride) {
        float4 a = x[i];
        float4 r;
        r.x = quant_one(a.x, scale, bias, lutb);
        r.y = quant_one(a.y, scale, bias, lutb);
        r.z = quant_one(a.z, scale, bias, lutb);
        r.w = quant_one(a.w, scale, bias, lutb);
        out[i] = r;
    }
}

// ---------------------------------------------------------------------------
extern "C" void kernel_launch(void* const* d_in, const int* in_sizes, int n_in,
                              void* d_out, int out_size)
{
    const float* x      = (const float*)d_in[0];
    const float* center = (const float*)d_in[1];
    float*       out    = (float*)d_out;

    (void)n_in;
    const int n  = in_sizes[0];
    const int n4 = n >> 2;

    // opt-in to 64 KB dynamic shared memory (idempotent, capture-safe)
    cudaFuncSetAttribute(quant_main_kernel,
                         cudaFuncAttributeMaxDynamicSharedMemorySize, LUT_BYTES);

    quant_prep_kernel<<<1, 256>>>(center);

    const int threads = 1024;
    const int blocks  = 296;   // 2 CTAs/SM x 148 SMs
    quant_main_kernel<<<blocks, threads, LUT_BYTES>>>(
        (const float4*)x, (float4*)out, n4);
}

// round 2
// speedup vs baseline: 1.5625x; 1.5625x over previous
#include <cuda_runtime.h>
#include <cuda_bf16.h>
#include <math.h>

// ============================================================================
// quantizer: out = center[argmin_m |x - center[m]|]   (== W_hard; reference's
// (W_hard - W_soft) + W_soft equals W_hard up to 1 ulp).
//
// R2: per-element shared traffic cut 16B -> 1B. LUT stores only a 1-byte
// region index b (region of the cell's lower edge). Exact fp32 crossovers and
// sorted centers live one-per-lane in registers; the boundary resolve and the
// final center gather are warp shuffles:
//   r = b + (x >= shfl(cross, b));  out = shfl(center, r)
// Loop bounds are warp-uniform (wb = i - lane) so shuffles are always
// full-warp; tail iterations predicate only the LDG/STG.
// ============================================================================

#define LUT_SIZE 8192

__device__ unsigned char g_blut[LUT_SIZE];
__device__ float g_scale, g_bias;
__device__ float g_cross[16];   // g_cross[15] = +inf
__device__ float g_csort[16];   // sorted centers

// ---------------------------------------------------------------------------
// Prep: thread 0 sorts; lanes 0..14 bisect exact crossovers in parallel;
// 256 threads fill the 8 KB byte-LUT.
// ---------------------------------------------------------------------------
__global__ void quant_prep_kernel(const float* __restrict__ center)
{
    __shared__ float s_c[16];
    __shared__ int   s_oi[16];
    __shared__ float s_cross[16];
    __shared__ float s_scale, s_bias;
    const int tid = threadIdx.x;

    if (tid == 0) {
        float c[16]; int oi[16];
        for (int i = 0; i < 16; i++) { c[i] = center[i]; oi[i] = i; }
        // stable insertion sort, keep original indices for argmin tie rule
        for (int i = 1; i < 16; i++) {
            float v = c[i]; int ix = oi[i]; int j = i - 1;
            while (j >= 0 && c[j] > v) { c[j+1] = c[j]; oi[j+1] = oi[j]; j--; }
            c[j+1] = v; oi[j+1] = ix;
        }
        for (int i = 0; i < 16; i++) { s_c[i] = c[i]; s_oi[i] = oi[i]; }
        float mid0  = 0.5f * (c[0]  + c[1]);
        float mid14 = 0.5f * (c[14] + c[15]);
        float span  = mid14 - mid0;
        if (!(span > 0.0f)) span = 1e-6f;
        float step  = span / (float)(LUT_SIZE - 160);  // 80-cell margins
        float lo    = mid0 - 80.0f * step;
        float scale = 1.0f / step;                     // 1 code unit per cell
        float bias  = -lo * scale;
        s_scale = scale; s_bias = bias;
        g_scale = scale; g_bias = bias;
    }
    __syncthreads();

    if (tid < 16) {
        float cv;
        if (tid < 15) {
            // Exact fp32 flip point of pick_left for pair (k, k+1).
            // pick_left is monotone (true..true, tie-plateau, false..false),
            // bracket [c_k, c_{k+1}] is valid: bisect to adjacent floats.
            float cl = s_c[tid], cr = s_c[tid + 1];
            int   ol = s_oi[tid], orr = s_oi[tid + 1];
            float a = cl, b = cr;
            for (int it = 0; it < 60; it++) {
                float m = 0.5f * (a + b);
                if (m <= a || m >= b) break;
                float dl = fabsf(m - cl), dr = fabsf(m - cr);
                bool pl = (dl < dr) || (dl == dr && ol < orr);
                if (pl) a = m; else b = m;
            }
            cv = b;                         // smallest x picking the RIGHT center
        } else {
            cv = __int_as_float(0x7f800000);  // +inf sentinel for region 15
        }
        s_cross[tid] = cv;
        g_cross[tid] = cv;
        g_csort[tid] = s_c[tid];
    }
    __syncthreads();

    const float scale = s_scale, bias = s_bias;
    const float inv = 1.0f / scale;
    for (int i = tid; i < LUT_SIZE; i += blockDim.x) {
        // conservative lower x-edge of cell i (rn window [i-0.5,i+0.5] + margin)
        float xlo = ((float)i - 1.5f - bias) * inv;
        int b = 0;
        #pragma unroll
        for (int k = 0; k < 15; k++) b += (s_cross[k] <= xlo) ? 1 : 0;
        g_blut[i] = (unsigned char)b;
    }
}

// ---------------------------------------------------------------------------
// Main kernel
// ---------------------------------------------------------------------------
__device__ __forceinline__ float qone(float x, float scale, float bias,
                                      const unsigned char* __restrict__ sblut,
                                      float crossv, float centv)
{
    float t = fmaf(x, scale, bias);
    unsigned code = __float2uint_rn(t);            // saturates negatives/NaN->0
    code = umin(code, (unsigned)(LUT_SIZE - 1));
    int b = (int)sblut[code];
    float thr = __shfl_sync(0xffffffffu, crossv, b);
    int r = b + ((x >= thr) ? 1 : 0);              // r <= 15 (cross[15]=+inf)
    return __shfl_sync(0xffffffffu, centv, r);
}

extern "C" __global__ void __launch_bounds__(1024, 2)
quant_main_kernel(const float4* __restrict__ x, float4* __restrict__ out, int n4)
{
    __shared__ unsigned char sblut[LUT_SIZE];
    const int tid = threadIdx.x;
    {
        int4* d = (int4*)sblut;
        const int4* s = (const int4*)g_blut;
        #pragma unroll
        for (int i = tid; i < LUT_SIZE / 16; i += 1024) d[i] = s[i];
    }
    const float scale = g_scale;
    const float bias  = g_bias;
    const int   lane  = tid & 31;
    const float crossv = g_cross[lane & 15];   // per-lane crossover table
    const float centv  = g_csort[lane & 15];   // per-lane center table
    __syncthreads();

    const int stride = gridDim.x * blockDim.x;
    int i  = blockIdx.x * blockDim.x + tid;
    int wb = i - lane;                         // warp-uniform base index

    // main loop: warp-uniform trip count, 2x float4 deep
    for (; wb + 31 + stride < n4; i += 2 * stride, wb += 2 * stride) {
        float4 a = x[i];
        float4 b = x[i + stride];
        float4 ra, rb;
        ra.x = qone(a.x, scale, bias, sblut, crossv, centv);
        ra.y = qone(a.y, scale, bias, sblut, crossv, centv);
        ra.z = qone(a.z, scale, bias, sblut, crossv, centv);
        ra.w = qone(a.w, scale, bias, sblut, crossv, centv);
        rb.x = qone(b.x, scale, bias, sblut, crossv, centv);
        rb.y = qone(b.y, scale, bias, sblut, crossv, centv);
        rb.z = qone(b.z, scale, bias, sblut, crossv, centv);
        rb.w = qone(b.w, scale, bias, sblut, crossv, centv);
        out[i]          = ra;
        out[i + stride] = rb;
    }
    // tail: still full-warp (shuffles need all lanes); predicate LDG/STG only
    for (; wb < n4; i += stride, wb += stride) {
        const bool v = (i < n4);
        float4 a = v ? x[i] : make_float4(0.f, 0.f, 0.f, 0.f);
        float4 r;
        r.x = qone(a.x, scale, bias, sblut, crossv, centv);
        r.y = qone(a.y, scale, bias, sblut, crossv, centv);
        r.z = qone(a.z, scale, bias, sblut, crossv, centv);
        r.w = qone(a.w, scale, bias, sblut, crossv, centv);
        if (v) out[i] = r;
    }
}

// ---------------------------------------------------------------------------
extern "C" void kernel_launch(void* const* d_in, const int* in_sizes, int n_in,
                              void* d_out, int out_size)
{
    const float* x      = (const float*)d_in[0];
    const float* center = (const float*)d_in[1];
    float*       out    = (float*)d_out;
    (void)n_in; (void)out_size;

    const int n  = in_sizes[0];
    const int n4 = n >> 2;

    quant_prep_kernel<<<1, 256>>>(center);

    const int threads = 1024;
    const int blocks  = 296;   // 2 CTAs/SM x 148 SMs
    quant_main_kernel<<<blocks, threads>>>((const float4*)x, (float4*)out, n4);
}